// round 1
// baseline (speedup 1.0000x reference)
#include <cuda_runtime.h>
#include <math.h>

#define BQ 8
#define NN 3072
#define HDIM 64
#define KNEI 16
#define BN (BQ*NN)

// ---- scratch (device globals: allocation-free) ----
__device__ float g_h [BN*HDIM];
__device__ float g_h2[BN*HDIM];
__device__ float g_xx[BN];
__device__ int   g_idx[BN*KNEI];
__device__ float g_A[BN*128];
__device__ float g_C[BN*128];

__device__ __forceinline__ float elu_f(float v){ return v > 0.f ? v : expm1f(v); }

// ---------------------------------------------------------------- embed
__global__ void k_embed(const float* __restrict__ x, const float* __restrict__ dn,
                        const float* __restrict__ Wi, const float* __restrict__ bi)
{
    int i = blockIdx.x * blockDim.x + threadIdx.x;
    if (i >= BN*HDIM) return;
    int node = i >> 6, j = i & 63;
    float s = bi[j];
#pragma unroll
    for (int d = 0; d < 3; d++)
        s += x[node*3 + d] * dn[d] * Wi[d*HDIM + j];
    g_h[i] = elu_f(s);
}

// ---------------------------------------------------------------- ||h||^2
__global__ void k_xx(int src)
{
    const float* h = src ? g_h2 : g_h;
    int gw   = (blockIdx.x * blockDim.x + threadIdx.x) >> 5;
    int lane = threadIdx.x & 31;
    if (gw >= BN) return;
    const float* p = h + gw*HDIM;
    float s = 0.f;
#pragma unroll
    for (int d = lane; d < HDIM; d += 32) { float v = p[d]; s += v*v; }
#pragma unroll
    for (int o = 16; o > 0; o >>= 1) s += __shfl_xor_sync(0xffffffffu, s, o);
    if (lane == 0) g_xx[gw] = s;
}

// ---------------------------------------------------------------- knn (top-16 smallest d2)
__global__ void __launch_bounds__(128) k_knn(int src)
{
    const float* h = src ? g_h2 : g_h;
    __shared__ float sc[64*64];
    __shared__ float sxx[64];

    int b = blockIdx.y;
    int q = blockIdx.x * 128 + threadIdx.x;       // query within batch
    const float* hb = h + (size_t)b*NN*HDIM;

    float hq[64];
    {
        const float4* p = (const float4*)(hb + q*HDIM);
#pragma unroll
        for (int t = 0; t < 16; t++) {
            float4 v = p[t];
            hq[4*t+0] = v.x; hq[4*t+1] = v.y; hq[4*t+2] = v.z; hq[4*t+3] = v.w;
        }
    }
    float qxx = g_xx[b*NN + q];

    float dist[KNEI]; int idxs[KNEI];
#pragma unroll
    for (int i = 0; i < KNEI; i++) { dist[i] = 3.0e38f; idxs[i] = 0; }

    for (int c0 = 0; c0 < NN; c0 += 64) {
        __syncthreads();
        for (int i = threadIdx.x; i < 64*64; i += 128) sc[i] = hb[c0*HDIM + i];
        if (threadIdx.x < 64) sxx[threadIdx.x] = g_xx[b*NN + c0 + threadIdx.x];
        __syncthreads();

#pragma unroll 1
        for (int c = 0; c < 64; c++) {
            const float4* cv = (const float4*)(sc + c*64);
            float s0=0.f, s1=0.f, s2=0.f, s3=0.f;
#pragma unroll
            for (int t = 0; t < 16; t++) {
                float4 v = cv[t];
                s0 += hq[4*t+0]*v.x; s1 += hq[4*t+1]*v.y;
                s2 += hq[4*t+2]*v.z; s3 += hq[4*t+3]*v.w;
            }
            float d2 = qxx + sxx[c] - 2.f*((s0+s1)+(s2+s3));
            if (d2 < dist[KNEI-1]) {
                int ci = c0 + c;
#pragma unroll
                for (int i = KNEI-1; i >= 0; i--) {
                    if (d2 < dist[i]) {
                        if (i < KNEI-1) { dist[i+1] = dist[i]; idxs[i+1] = idxs[i]; }
                        dist[i] = d2; idxs[i] = ci;
                    }
                }
            }
        }
    }
    int* op = g_idx + (size_t)(b*NN + q)*KNEI;
#pragma unroll
    for (int i = 0; i < KNEI; i++) op[i] = idxs[i];
}

// ---------------------------------------------------------------- per-node A/C precompute
// A = h @ (W1[0:64]-W1[64:128]) + b1 ;  C = h @ W1[64:128]
__global__ void __launch_bounds__(128) k_ac(int src, const float* __restrict__ W1l,
                                            const float* __restrict__ b1l)
{
    __shared__ float sbuf[128*64];            // 32 KB, reused
    const float* h = src ? g_h2 : g_h;
    int tid = threadIdx.x;
    int nodeBase = blockIdx.x * 128;

    // stage h tile (coalesced), then pull own row to registers
    for (int i = tid; i < 128*64; i += 128) sbuf[i] = h[(size_t)nodeBase*HDIM + i];
    __syncthreads();
    float hr[64];
#pragma unroll
    for (int d = 0; d < 64; d++) hr[d] = sbuf[tid*64 + d];
    __syncthreads();

    int node = nodeBase + tid;
    for (int half = 0; half < 2; half++) {
        int jb = half * 64;
        for (int i = tid; i < 64*64; i += 128) {
            int d = i >> 6, j = i & 63;
            sbuf[i]        = W1l[d*128 + jb + j];          // W1 top
            sbuf[4096 + i] = W1l[(d+64)*128 + jb + j];     // W1 bottom
        }
        __syncthreads();
#pragma unroll 1
        for (int j = 0; j < 64; j++) {
            float a = 0.f, c = 0.f;
#pragma unroll
            for (int d = 0; d < 64; d++) {
                float wt = sbuf[d*64 + j];
                float wb = sbuf[4096 + d*64 + j];
                a += hr[d] * (wt - wb);
                c += hr[d] * wb;
            }
            g_A[(size_t)node*128 + jb + j] = a + b1l[jb + j];
            g_C[(size_t)node*128 + jb + j] = c;
        }
        __syncthreads();
    }
}

// ---------------------------------------------------------------- edge aggregation
// per node: m1[k] = elu(A[n] + C[idx[k]]); h'[j] = sum_k elu( m1[k]@W2[:,j] + b2[j] )
__global__ void __launch_bounds__(128) k_edge(int dst, const float* __restrict__ W2l,
                                              const float* __restrict__ b2l)
{
    __shared__ float sW2[128*64];       // 32 KB  W2[d][j]
    __shared__ float sm1[2][16*128];    // 16 KB  per-node m1

    int tid   = threadIdx.x;
    int local = tid >> 6;               // node within block (0/1)
    int j     = tid & 63;
    int node  = blockIdx.x * 2 + local;
    int b     = node / NN;

    for (int i = tid; i < 128*64; i += 128) sW2[i] = W2l[i];

    // phase 1: m1 into shared
    const float* A = g_A + (size_t)node*128;
    const int*  ip = g_idx + (size_t)node*KNEI;
#pragma unroll 1
    for (int k = 0; k < KNEI; k++) {
        int nbr = ip[k];
        const float* C = g_C + ((size_t)(b*NN + nbr))*128;
        sm1[local][k*128 + j]      = elu_f(A[j]      + C[j]);
        sm1[local][k*128 + j + 64] = elu_f(A[j + 64] + C[j + 64]);
    }
    __syncthreads();

    // phase 2: 16 accumulators, W2 column j, m1 broadcast
    float s[KNEI];
#pragma unroll
    for (int k = 0; k < KNEI; k++) s[k] = 0.f;

#pragma unroll 1
    for (int d0 = 0; d0 < 128; d0 += 4) {
        float w0 = sW2[(d0+0)*64 + j];
        float w1 = sW2[(d0+1)*64 + j];
        float w2 = sW2[(d0+2)*64 + j];
        float w3 = sW2[(d0+3)*64 + j];
#pragma unroll
        for (int k = 0; k < KNEI; k++) {
            float4 m = *(const float4*)&sm1[local][k*128 + d0];
            s[k] += m.x*w0; s[k] += m.y*w1; s[k] += m.z*w2; s[k] += m.w*w3;
        }
    }
    float bb = b2l[j];
    float acc = 0.f;
#pragma unroll
    for (int k = 0; k < KNEI; k++) acc += elu_f(s[k] + bb);

    float* hd = dst ? g_h2 : g_h;
    hd[(size_t)node*HDIM + j] = acc;
}

// ---------------------------------------------------------------- maxpool + head MLP
__global__ void k_final(const float* __restrict__ Wo1, const float* __restrict__ bo1,
                        const float* __restrict__ Wo2, const float* __restrict__ bo2,
                        const float* __restrict__ Wo3, const float* __restrict__ bo3,
                        float* __restrict__ out)
{
    __shared__ float red[512];
    __shared__ float o1[64], o2[64];
    int b = blockIdx.x, tid = threadIdx.x;
    int j = tid & 63, r = tid >> 6;                  // 8 row-lanes

    const float* h = g_h + (size_t)b*NN*HDIM;
    float m = -3.0e38f;
    for (int n = r; n < NN; n += 8) m = fmaxf(m, h[(size_t)n*HDIM + j]);
    red[tid] = m;
    __syncthreads();
    if (tid < 64) {
        float mm = red[tid];
#pragma unroll
        for (int rr = 1; rr < 8; rr++) mm = fmaxf(mm, red[rr*64 + tid]);
        red[tid] = mm;                                // pooled[j]
    }
    __syncthreads();
    if (tid < 64) {
        float s = bo1[tid];
#pragma unroll
        for (int d = 0; d < 64; d++) s += red[d] * Wo1[d*64 + tid];
        o1[tid] = elu_f(s);
    }
    __syncthreads();
    if (tid < 64) {
        float s = bo2[tid];
#pragma unroll
        for (int d = 0; d < 64; d++) s += o1[d] * Wo2[d*64 + tid];
        o2[tid] = elu_f(s);
    }
    __syncthreads();
    if (tid == 0) {
        float s = bo3[0];
#pragma unroll
        for (int d = 0; d < 64; d++) s += o2[d] * Wo3[d];
        out[b] = s;
    }
}

// ---------------------------------------------------------------- host
extern "C" void kernel_launch(void* const* d_in, const int* in_sizes, int n_in,
                              void* d_out, int out_size)
{
    const float* x   = (const float*)d_in[0];
    const float* dn  = (const float*)d_in[1];
    const float* Wi  = (const float*)d_in[2];
    const float* bi  = (const float*)d_in[3];
    const float* W1  = (const float*)d_in[4];
    const float* b1  = (const float*)d_in[5];
    const float* W2  = (const float*)d_in[6];
    const float* b2  = (const float*)d_in[7];
    const float* Wo1 = (const float*)d_in[8];
    const float* bo1 = (const float*)d_in[9];
    const float* Wo2 = (const float*)d_in[10];
    const float* bo2 = (const float*)d_in[11];
    const float* Wo3 = (const float*)d_in[12];
    const float* bo3 = (const float*)d_in[13];
    float* out = (float*)d_out;

    k_embed<<<(BN*HDIM + 255)/256, 256>>>(x, dn, Wi, bi);

    for (int l = 0; l < 2; l++) {
        int src = l;          // 0 -> g_h, 1 -> g_h2
        int dst = 1 - l;
        k_xx <<<(BN*32 + 255)/256, 256>>>(src);
        k_knn<<<dim3(NN/128, BQ), 128>>>(src);
        k_ac <<<BN/128, 128>>>(src, W1 + l*128*128, b1 + l*128);
        k_edge<<<BN/2, 128>>>(dst, W2 + l*128*64, b2 + l*64);
    }
    k_final<<<BQ, 512>>>(Wo1, bo1, Wo2, bo2, Wo3, bo3, out);
}

// round 3
// speedup vs baseline: 1.4970x; 1.4970x over previous
#include <cuda_runtime.h>
#include <math.h>

#define BQ 8
#define NN 3072
#define HDIM 64
#define KNEI 16
#define BN (BQ*NN)

typedef unsigned long long u64;

// ---- scratch (device globals: allocation-free) ----
__device__ float g_h [BN*HDIM];
__device__ float g_h2[BN*HDIM];
__device__ float g_xx[BN];
__device__ int   g_idx[BN*KNEI];
__device__ float g_A[BN*128];
__device__ float g_C[BN*128];
__device__ float g_d2p[BN*32];
__device__ int   g_i2p[BN*32];
__device__ float g_pmax[BQ*24*64];

__device__ __forceinline__ float elu_f(float v){ return v > 0.f ? v : expm1f(v); }

__device__ __forceinline__ u64 ffma2(u64 a, u64 b, u64 c){
    u64 d; asm("fma.rn.f32x2 %0,%1,%2,%3;" : "=l"(d) : "l"(a), "l"(b), "l"(c)); return d;
}
__device__ __forceinline__ u64 packf2(float lo, float hi){
    u64 r; asm("mov.b64 %0,{%1,%2};" : "=l"(r) : "f"(lo), "f"(hi)); return r;
}
__device__ __forceinline__ float2 unpk(u64 v){
    float2 r; asm("mov.b64 {%0,%1},%2;" : "=f"(r.x), "=f"(r.y) : "l"(v)); return r;
}

// ---------------------------------------------------------------- embed
__global__ void k_embed(const float* __restrict__ x, const float* __restrict__ dn,
                        const float* __restrict__ Wi, const float* __restrict__ bi)
{
    int i = blockIdx.x * blockDim.x + threadIdx.x;
    if (i >= BN*HDIM) return;
    int node = i >> 6, j = i & 63;
    float s = bi[j];
#pragma unroll
    for (int d = 0; d < 3; d++)
        s += x[node*3 + d] * dn[d] * Wi[d*HDIM + j];
    g_h[i] = elu_f(s);
}

// ---------------------------------------------------------------- ||h||^2
__global__ void k_xx(int src)
{
    const float* h = src ? g_h2 : g_h;
    int gw   = (blockIdx.x * blockDim.x + threadIdx.x) >> 5;
    int lane = threadIdx.x & 31;
    if (gw >= BN) return;
    const float* p = h + gw*HDIM;
    float s = 0.f;
#pragma unroll
    for (int d = lane; d < HDIM; d += 32) { float v = p[d]; s += v*v; }
#pragma unroll
    for (int o = 16; o > 0; o >>= 1) s += __shfl_xor_sync(0xffffffffu, s, o);
    if (lane == 0) g_xx[gw] = s;
}

// ---------------------------------------------------------------- knn partial (candidate split 2-way)
__global__ void __launch_bounds__(128) k_knn(int src)
{
    const float* h = src ? g_h2 : g_h;
    __shared__ __align__(16) float sc[64*64];
    __shared__ float sxx[64];

    int b = blockIdx.y;
    int q = blockIdx.x * 128 + threadIdx.x;
    int zc = blockIdx.z * (NN/2);             // candidate range start
    const float* hb = h + (size_t)b*NN*HDIM;

    u64 hq2[32];
    {
        const float4* p = (const float4*)(hb + q*HDIM);
#pragma unroll
        for (int t = 0; t < 16; t++) {
            float4 v = p[t];
            hq2[2*t]   = packf2(v.x, v.y);
            hq2[2*t+1] = packf2(v.z, v.w);
        }
    }
    float qxx = g_xx[b*NN + q];

    float dist[KNEI]; int idxs[KNEI];
#pragma unroll
    for (int i = 0; i < KNEI; i++) { dist[i] = 3.0e38f; idxs[i] = 0; }

    for (int c0 = zc; c0 < zc + NN/2; c0 += 64) {
        __syncthreads();
        for (int i = threadIdx.x; i < 64*64; i += 128) sc[i] = hb[(size_t)c0*HDIM + i];
        if (threadIdx.x < 64) sxx[threadIdx.x] = g_xx[b*NN + c0 + threadIdx.x];
        __syncthreads();

#pragma unroll 1
        for (int c = 0; c < 64; c++) {
            const ulonglong2* cv = (const ulonglong2*)(sc + c*64);
            u64 a0 = 0ull, a1 = 0ull, a2 = 0ull, a3 = 0ull;
#pragma unroll
            for (int t = 0; t < 16; t++) {
                ulonglong2 m = cv[t];
                if (t & 1) { a2 = ffma2(hq2[2*t], m.x, a2); a3 = ffma2(hq2[2*t+1], m.y, a3); }
                else       { a0 = ffma2(hq2[2*t], m.x, a0); a1 = ffma2(hq2[2*t+1], m.y, a1); }
            }
            float2 f0 = unpk(a0), f1 = unpk(a1), f2 = unpk(a2), f3 = unpk(a3);
            float sum = ((f0.x+f0.y)+(f1.x+f1.y)) + ((f2.x+f2.y)+(f3.x+f3.y));
            float d2 = qxx + sxx[c] - 2.f*sum;
            if (d2 < dist[KNEI-1]) {
                int ci = c0 + c;
#pragma unroll
                for (int i = KNEI-1; i >= 0; i--) {
                    if (d2 < dist[i]) {
                        if (i < KNEI-1) { dist[i+1] = dist[i]; idxs[i+1] = idxs[i]; }
                        dist[i] = d2; idxs[i] = ci;
                    }
                }
            }
        }
    }
    size_t o = ((size_t)(b*NN + q)*2 + blockIdx.z)*16;
#pragma unroll
    for (int i = 0; i < KNEI; i++) { g_d2p[o+i] = dist[i]; g_i2p[o+i] = idxs[i]; }
}

// ---------------------------------------------------------------- merge 2 partial top-16 lists
__global__ void k_merge()
{
    int q = blockIdx.x * 256 + threadIdx.x;
    if (q >= BN) return;
    const float* dp = g_d2p + (size_t)q*32;
    const int*   ip = g_i2p + (size_t)q*32;
    float dist[KNEI]; int idxs[KNEI];
#pragma unroll
    for (int i = 0; i < KNEI; i++) { dist[i] = 3.0e38f; idxs[i] = 0; }
#pragma unroll 1
    for (int t = 0; t < 32; t++) {
        float d2 = dp[t]; int ci = ip[t];
        if (d2 < dist[KNEI-1]) {
#pragma unroll
            for (int i = KNEI-1; i >= 0; i--) {
                if (d2 < dist[i]) {
                    if (i < KNEI-1) { dist[i+1] = dist[i]; idxs[i+1] = idxs[i]; }
                    dist[i] = d2; idxs[i] = ci;
                }
            }
        }
    }
    int* op = g_idx + (size_t)q*KNEI;
#pragma unroll
    for (int i = 0; i < KNEI; i++) op[i] = idxs[i];
}

// ---------------------------------------------------------------- per-node A/C precompute (packed)
// A = h @ (W1[0:64]-W1[64:128]) + b1 ;  C = h @ W1[64:128]
__global__ void __launch_bounds__(128) k_ac(int src, const float* __restrict__ W1l,
                                            const float* __restrict__ b1l)
{
    __shared__ __align__(16) float sb[8192];          // 32 KB, reused: h tile -> weight halves
    const float* h = src ? g_h2 : g_h;
    int tid = threadIdx.x;
    size_t nodeBase = (size_t)blockIdx.x * 128;

    for (int i = tid; i < 8192; i += 128) sb[i] = h[nodeBase*HDIM + i];
    __syncthreads();
    u64 h2[64];
#pragma unroll
    for (int d = 0; d < 64; d++) { float v = sb[tid*64 + d]; h2[d] = packf2(v, v); }
    __syncthreads();

    int node = (int)nodeBase + tid;
    for (int half = 0; half < 2; half++) {
        int jb = half * 64;
        for (int i = tid; i < 4096; i += 128) {
            int d = i >> 6, jj = i & 63;
            sb[i]        = W1l[d*128 + jb + jj];          // wt  [d][jj]
            sb[4096 + i] = W1l[(d+64)*128 + jb + jj];     // wb
        }
        __syncthreads();
#pragma unroll 1
        for (int jg = 0; jg < 16; jg++) {
            int j0 = jg * 4;
            u64 a01 = 0ull, a23 = 0ull, c01 = 0ull, c23 = 0ull;
#pragma unroll
            for (int d = 0; d < 64; d++) {
                ulonglong2 wt = *(const ulonglong2*)&sb[d*64 + j0];
                ulonglong2 wb = *(const ulonglong2*)&sb[4096 + d*64 + j0];
                a01 = ffma2(h2[d], wt.x, a01); a23 = ffma2(h2[d], wt.y, a23);
                c01 = ffma2(h2[d], wb.x, c01); c23 = ffma2(h2[d], wb.y, c23);
            }
            float2 fa0 = unpk(a01), fa1 = unpk(a23), fc0 = unpk(c01), fc1 = unpk(c23);
            int jo = jb + j0;
            float* Ap = g_A + (size_t)node*128 + jo;
            float* Cp = g_C + (size_t)node*128 + jo;
            Ap[0] = fa0.x - fc0.x + b1l[jo+0];  Cp[0] = fc0.x;
            Ap[1] = fa0.y - fc0.y + b1l[jo+1];  Cp[1] = fc0.y;
            Ap[2] = fa1.x - fc1.x + b1l[jo+2];  Cp[2] = fc1.x;
            Ap[3] = fa1.y - fc1.y + b1l[jo+3];  Cp[3] = fc1.y;
        }
        __syncthreads();
    }
}

// ---------------------------------------------------------------- edge aggregation (packed)
__global__ void __launch_bounds__(128) k_edge(int dst, const float* __restrict__ W2l,
                                              const float* __restrict__ b2l)
{
    __shared__ float sW2[128*64];                 // 32 KB  W2[d][j]
    __shared__ __align__(16) float sm1[2][16*128];// 16 KB

    int tid   = threadIdx.x;
    int local = tid >> 6;
    int j     = tid & 63;
    int node  = blockIdx.x * 2 + local;
    int b     = node / NN;

    for (int i = tid; i < 128*64; i += 128) sW2[i] = W2l[i];

    // phase 1: m1 into shared
    const float* A = g_A + (size_t)node*128;
    const int*  ip = g_idx + (size_t)node*KNEI;
    float a0 = A[j], a1 = A[j + 64];
    int nbrs[KNEI];
#pragma unroll
    for (int k = 0; k < KNEI; k++) nbrs[k] = ip[k];
#pragma unroll 4
    for (int k = 0; k < KNEI; k++) {
        const float* C = g_C + ((size_t)(b*NN + nbrs[k]))*128;
        sm1[local][k*128 + j]      = elu_f(a0 + C[j]);
        sm1[local][k*128 + j + 64] = elu_f(a1 + C[j + 64]);
    }
    __syncthreads();

    // phase 2: packed accumulation, 16 packed accumulators
    u64 s2[KNEI];
#pragma unroll
    for (int k = 0; k < KNEI; k++) s2[k] = 0ull;

#pragma unroll 2
    for (int d0 = 0; d0 < 128; d0 += 4) {
        float w0 = sW2[(d0+0)*64 + j];
        float w1 = sW2[(d0+1)*64 + j];
        float w2 = sW2[(d0+2)*64 + j];
        float w3 = sW2[(d0+3)*64 + j];
        u64 w01 = packf2(w0, w1), w23 = packf2(w2, w3);
#pragma unroll
        for (int k = 0; k < KNEI; k++) {
            ulonglong2 m = *(const ulonglong2*)&sm1[local][k*128 + d0];
            s2[k] = ffma2(m.x, w01, s2[k]);
            s2[k] = ffma2(m.y, w23, s2[k]);
        }
    }
    float bb = b2l[j];
    float acc = 0.f;
#pragma unroll
    for (int k = 0; k < KNEI; k++) {
        float2 f = unpk(s2[k]);
        acc += elu_f(f.x + f.y + bb);
    }

    float* hd = dst ? g_h2 : g_h;
    hd[(size_t)node*HDIM + j] = acc;
}

// ---------------------------------------------------------------- two-stage maxpool
__global__ void k_pool()
{
    __shared__ float red[256];
    int b = blockIdx.y;
    int n0 = blockIdx.x * 128;
    int tid = threadIdx.x, j = tid & 63, r = tid >> 6;
    const float* h = g_h + ((size_t)b*NN + n0)*HDIM;
    float m = -3.0e38f;
    for (int n = r; n < 128; n += 4) m = fmaxf(m, h[(size_t)n*HDIM + j]);
    red[tid] = m;
    __syncthreads();
    if (tid < 64) {
        float mm = fmaxf(fmaxf(red[tid], red[64+tid]), fmaxf(red[128+tid], red[192+tid]));
        g_pmax[(b*24 + blockIdx.x)*64 + j] = mm;
    }
}

__global__ void k_final(const float* __restrict__ Wo1, const float* __restrict__ bo1,
                        const float* __restrict__ Wo2, const float* __restrict__ bo2,
                        const float* __restrict__ Wo3, const float* __restrict__ bo3,
                        float* __restrict__ out)
{
    __shared__ float pooled[64], o1[64], o2[64];
    int b = blockIdx.x, tid = threadIdx.x;
    float m = -3.0e38f;
#pragma unroll
    for (int p = 0; p < 24; p++) m = fmaxf(m, g_pmax[(b*24 + p)*64 + tid]);
    pooled[tid] = m;
    __syncthreads();
    {
        float s = bo1[tid];
#pragma unroll
        for (int d = 0; d < 64; d++) s += pooled[d] * Wo1[d*64 + tid];
        o1[tid] = elu_f(s);
    }
    __syncthreads();
    {
        float s = bo2[tid];
#pragma unroll
        for (int d = 0; d < 64; d++) s += o1[d] * Wo2[d*64 + tid];
        o2[tid] = elu_f(s);
    }
    __syncthreads();
    if (tid == 0) {
        float s = bo3[0];
#pragma unroll
        for (int d = 0; d < 64; d++) s += o2[d] * Wo3[d];
        out[b] = s;
    }
}

// ---------------------------------------------------------------- host
extern "C" void kernel_launch(void* const* d_in, const int* in_sizes, int n_in,
                              void* d_out, int out_size)
{
    const float* x   = (const float*)d_in[0];
    const float* dn  = (const float*)d_in[1];
    const float* Wi  = (const float*)d_in[2];
    const float* bi  = (const float*)d_in[3];
    const float* W1  = (const float*)d_in[4];
    const float* b1  = (const float*)d_in[5];
    const float* W2  = (const float*)d_in[6];
    const float* b2  = (const float*)d_in[7];
    const float* Wo1 = (const float*)d_in[8];
    const float* bo1 = (const float*)d_in[9];
    const float* Wo2 = (const float*)d_in[10];
    const float* bo2 = (const float*)d_in[11];
    const float* Wo3 = (const float*)d_in[12];
    const float* bo3 = (const float*)d_in[13];
    float* out = (float*)d_out;

    k_embed<<<(BN*HDIM + 255)/256, 256>>>(x, dn, Wi, bi);

    for (int l = 0; l < 2; l++) {
        int src = l;
        int dst = 1 - l;
        k_xx  <<<(BN*32 + 255)/256, 256>>>(src);
        k_knn <<<dim3(NN/128, BQ, 2), 128>>>(src);
        k_merge<<<(BN + 255)/256, 256>>>();
        k_ac  <<<BN/128, 128>>>(src, W1 + l*128*128, b1 + l*128);
        k_edge<<<BN/2, 128>>>(dst, W2 + l*128*64, b2 + l*64);
    }
    k_pool <<<dim3(24, BQ), 256>>>();
    k_final<<<BQ, 64>>>(Wo1, bo1, Wo2, bo2, Wo3, bo3, out);
}

// round 4
// speedup vs baseline: 1.7091x; 1.1417x over previous
#include <cuda_runtime.h>
#include <math.h>

#define BQ 8
#define NN 3072
#define HDIM 64
#define KNEI 16
#define BN (BQ*NN)
#define ZSPLIT 6

typedef unsigned long long u64;

// ---- scratch (device globals: allocation-free) ----
__device__ float g_h [BN*HDIM];
__device__ float g_h2[BN*HDIM];
__device__ float g_xx[BN];
__device__ int   g_idx[BN*KNEI];
__device__ float g_A[BN*128];
__device__ float g_C[BN*128];
__device__ __align__(16) float g_d2p[BN*ZSPLIT*KNEI];
__device__ __align__(16) int   g_i2p[BN*ZSPLIT*KNEI];
__device__ float g_pmax[BQ*24*64];

__device__ __forceinline__ float elu_f(float v){ return v > 0.f ? v : expm1f(v); }

__device__ __forceinline__ u64 ffma2(u64 a, u64 b, u64 c){
    u64 d; asm("fma.rn.f32x2 %0,%1,%2,%3;" : "=l"(d) : "l"(a), "l"(b), "l"(c)); return d;
}
__device__ __forceinline__ u64 packf2(float lo, float hi){
    u64 r; asm("mov.b64 %0,{%1,%2};" : "=l"(r) : "f"(lo), "f"(hi)); return r;
}
__device__ __forceinline__ float2 unpk(u64 v){
    float2 r; asm("mov.b64 {%0,%1},%2;" : "=f"(r.x), "=f"(r.y) : "l"(v)); return r;
}

// ---------------------------------------------------------------- embed (+ fused ||h||^2)
__global__ void __launch_bounds__(256) k_embed(const float* __restrict__ x, const float* __restrict__ dn,
                        const float* __restrict__ Wi, const float* __restrict__ bi)
{
    __shared__ float part[8];
    int i = blockIdx.x * 256 + threadIdx.x;
    int node = i >> 6, j = i & 63;
    float s = bi[j];
#pragma unroll
    for (int d = 0; d < 3; d++)
        s += x[node*3 + d] * dn[d] * Wi[d*HDIM + j];
    float hv = elu_f(s);
    g_h[i] = hv;
    // fused xx: warp holds half a node (64 | 32)
    float sq = hv * hv;
#pragma unroll
    for (int o = 16; o > 0; o >>= 1) sq += __shfl_xor_sync(0xffffffffu, sq, o);
    if ((threadIdx.x & 31) == 0) part[threadIdx.x >> 5] = sq;
    __syncthreads();
    if (threadIdx.x < 4)
        g_xx[blockIdx.x*4 + threadIdx.x] = part[2*threadIdx.x] + part[2*threadIdx.x + 1];
}

// ---------------------------------------------------------------- knn partial (candidate split ZSPLIT-way)
__global__ void __launch_bounds__(128) k_knn(int src)
{
    const float* h = src ? g_h2 : g_h;
    __shared__ __align__(16) float sc[64*64];
    __shared__ float sxx[64];

    int b = blockIdx.y;
    int q = blockIdx.x * 128 + threadIdx.x;
    int zc = blockIdx.z * (NN/ZSPLIT);
    const float* hb = h + (size_t)b*NN*HDIM;

    u64 hq2[32];
    {
        const float4* p = (const float4*)(hb + q*HDIM);
#pragma unroll
        for (int t = 0; t < 16; t++) {
            float4 v = p[t];
            hq2[2*t]   = packf2(v.x, v.y);
            hq2[2*t+1] = packf2(v.z, v.w);
        }
    }
    float qxx = g_xx[b*NN + q];

    float dist[KNEI]; int idxs[KNEI];
#pragma unroll
    for (int i = 0; i < KNEI; i++) { dist[i] = 3.0e38f; idxs[i] = 0; }

    for (int c0 = zc; c0 < zc + NN/ZSPLIT; c0 += 64) {
        __syncthreads();
        for (int i = threadIdx.x; i < 64*64; i += 128) sc[i] = hb[(size_t)c0*HDIM + i];
        if (threadIdx.x < 64) sxx[threadIdx.x] = g_xx[b*NN + c0 + threadIdx.x];
        __syncthreads();

#pragma unroll 1
        for (int c = 0; c < 64; c++) {
            const ulonglong2* cv = (const ulonglong2*)(sc + c*64);
            u64 a0 = 0ull, a1 = 0ull, a2 = 0ull, a3 = 0ull;
#pragma unroll
            for (int t = 0; t < 16; t++) {
                ulonglong2 m = cv[t];
                if (t & 1) { a2 = ffma2(hq2[2*t], m.x, a2); a3 = ffma2(hq2[2*t+1], m.y, a3); }
                else       { a0 = ffma2(hq2[2*t], m.x, a0); a1 = ffma2(hq2[2*t+1], m.y, a1); }
            }
            float2 f0 = unpk(a0), f1 = unpk(a1), f2 = unpk(a2), f3 = unpk(a3);
            float sum = ((f0.x+f0.y)+(f1.x+f1.y)) + ((f2.x+f2.y)+(f3.x+f3.y));
            float d2 = qxx + sxx[c] - 2.f*sum;
            if (d2 < dist[KNEI-1]) {
                int ci = c0 + c;
#pragma unroll
                for (int i = KNEI-1; i >= 0; i--) {
                    if (d2 < dist[i]) {
                        if (i < KNEI-1) { dist[i+1] = dist[i]; idxs[i+1] = idxs[i]; }
                        dist[i] = d2; idxs[i] = ci;
                    }
                }
            }
        }
    }
    size_t o = ((size_t)(b*NN + q)*ZSPLIT + blockIdx.z)*KNEI;
#pragma unroll
    for (int i = 0; i < KNEI; i++) { g_d2p[o+i] = dist[i]; g_i2p[o+i] = idxs[i]; }
}

// ---------------------------------------------------------------- merge ZSPLIT partial top-16 lists
__global__ void k_merge()
{
    int q = blockIdx.x * 256 + threadIdx.x;
    if (q >= BN) return;
    const float4* dp = (const float4*)(g_d2p + (size_t)q*(ZSPLIT*KNEI));
    const int4*   ip = (const int4*)  (g_i2p + (size_t)q*(ZSPLIT*KNEI));
    float dist[KNEI]; int idxs[KNEI];
#pragma unroll
    for (int i = 0; i < KNEI; i++) { dist[i] = 3.0e38f; idxs[i] = 0; }
#pragma unroll 1
    for (int t = 0; t < ZSPLIT*KNEI/4; t++) {
        float4 d4 = dp[t]; int4 i4 = ip[t];
        float dv[4] = {d4.x, d4.y, d4.z, d4.w};
        int   iv[4] = {i4.x, i4.y, i4.z, i4.w};
#pragma unroll
        for (int u = 0; u < 4; u++) {
            float d2 = dv[u];
            if (d2 < dist[KNEI-1]) {
                int ci = iv[u];
#pragma unroll
                for (int i = KNEI-1; i >= 0; i--) {
                    if (d2 < dist[i]) {
                        if (i < KNEI-1) { dist[i+1] = dist[i]; idxs[i+1] = idxs[i]; }
                        dist[i] = d2; idxs[i] = ci;
                    }
                }
            }
        }
    }
    int* op = g_idx + (size_t)q*KNEI;
#pragma unroll
    for (int i = 0; i < KNEI; i++) op[i] = idxs[i];
}

// ---------------------------------------------------------------- per-node A/C precompute
// A = h @ (W1[0:64]-W1[64:128]) + b1 ;  C = h @ W1[64:128]
// thread=(node_local, j); 1024 threads, 16 nodes/block in 2 passes of 8
__global__ void __launch_bounds__(1024) k_ac(int src, const float* __restrict__ W1l,
                                             const float* __restrict__ b1l)
{
    __shared__ __align__(16) u64 sW[8192];   // [half][d2 0..31][j 0..127]  64KB
    __shared__ u64 sh[8][32];
    const float* h = src ? g_h2 : g_h;
    int tid = threadIdx.x;

    for (int i = tid; i < 8192; i += 1024) {
        int half = i >> 12;
        int r = i & 4095;
        int d2 = r >> 7, j = r & 127;
        int d = half*64 + 2*d2;
        sW[i] = packf2(W1l[d*128 + j], W1l[(d+1)*128 + j]);
    }

    int j = tid & 127, nl = tid >> 7;        // 8 nodes per pass
    float bj = b1l[j];
    size_t base = (size_t)blockIdx.x * 16;

#pragma unroll
    for (int pass = 0; pass < 2; pass++) {
        size_t n0 = base + pass*8;
        __syncthreads();
        if (tid < 256) {
            int nn = tid >> 5, d2 = tid & 31;
            const float* hp = h + (n0 + nn)*HDIM + 2*d2;
            sh[nn][d2] = packf2(hp[0], hp[1]);
        }
        __syncthreads();
        u64 a2 = 0ull, c2 = 0ull;
#pragma unroll
        for (int d2 = 0; d2 < 32; d2++) {
            u64 hv = sh[nl][d2];
            a2 = ffma2(hv, sW[d2*128 + j], a2);          // top
            c2 = ffma2(hv, sW[4096 + d2*128 + j], c2);   // bottom
        }
        float2 fa = unpk(a2), fc = unpk(c2);
        float c = fc.x + fc.y;
        float a = fa.x + fa.y;
        size_t node = n0 + nl;
        g_A[node*128 + j] = a - c + bj;
        g_C[node*128 + j] = c;
    }
}

// ---------------------------------------------------------------- edge aggregation (4 nodes/block, fused xx)
__global__ void __launch_bounds__(256) k_edge(int dst, const float* __restrict__ W2l,
                                              const float* __restrict__ b2l)
{
    __shared__ float sW2[128*64];                  // 32 KB  W2[d][j]
    __shared__ __align__(16) float sm1[4][16*128]; // 32 KB
    __shared__ float sxr[8];

    int tid   = threadIdx.x;
    int local = tid >> 6;
    int j     = tid & 63;
    size_t node = (size_t)blockIdx.x * 4 + local;
    int b     = (int)(node / NN);

    for (int i = tid; i < 128*64; i += 256) sW2[i] = W2l[i];

    // phase 1: m1 into shared
    const float* A = g_A + node*128;
    const int*  ip = g_idx + node*KNEI;
    float a0 = A[j], a1 = A[j + 64];
    int nbrs[KNEI];
#pragma unroll
    for (int k = 0; k < KNEI; k++) nbrs[k] = ip[k];
#pragma unroll 4
    for (int k = 0; k < KNEI; k++) {
        const float* C = g_C + ((size_t)(b*NN + nbrs[k]))*128;
        sm1[local][k*128 + j]      = elu_f(a0 + C[j]);
        sm1[local][k*128 + j + 64] = elu_f(a1 + C[j + 64]);
    }
    __syncthreads();

    // phase 2: packed accumulation
    u64 s2[KNEI];
#pragma unroll
    for (int k = 0; k < KNEI; k++) s2[k] = 0ull;

#pragma unroll 2
    for (int d0 = 0; d0 < 128; d0 += 4) {
        float w0 = sW2[(d0+0)*64 + j];
        float w1 = sW2[(d0+1)*64 + j];
        float w2 = sW2[(d0+2)*64 + j];
        float w3 = sW2[(d0+3)*64 + j];
        u64 w01 = packf2(w0, w1), w23 = packf2(w2, w3);
#pragma unroll
        for (int k = 0; k < KNEI; k++) {
            ulonglong2 m = *(const ulonglong2*)&sm1[local][k*128 + d0];
            s2[k] = ffma2(m.x, w01, s2[k]);
            s2[k] = ffma2(m.y, w23, s2[k]);
        }
    }
    float bb = b2l[j];
    float acc = 0.f;
#pragma unroll
    for (int k = 0; k < KNEI; k++) {
        float2 f = unpk(s2[k]);
        acc += elu_f(f.x + f.y + bb);
    }

    float* hd = dst ? g_h2 : g_h;
    hd[node*HDIM + j] = acc;

    // fused xx for next layer
    float sq = acc * acc;
#pragma unroll
    for (int o = 16; o > 0; o >>= 1) sq += __shfl_xor_sync(0xffffffffu, sq, o);
    if ((tid & 31) == 0) sxr[tid >> 5] = sq;
    __syncthreads();
    if (tid < 4)
        g_xx[blockIdx.x*4 + tid] = sxr[2*tid] + sxr[2*tid + 1];
}

// ---------------------------------------------------------------- two-stage maxpool
__global__ void k_pool()
{
    __shared__ float red[256];
    int b = blockIdx.y;
    int n0 = blockIdx.x * 128;
    int tid = threadIdx.x, j = tid & 63, r = tid >> 6;
    const float* h = g_h + ((size_t)b*NN + n0)*HDIM;
    float m = -3.0e38f;
    for (int n = r; n < 128; n += 4) m = fmaxf(m, h[(size_t)n*HDIM + j]);
    red[tid] = m;
    __syncthreads();
    if (tid < 64) {
        float mm = fmaxf(fmaxf(red[tid], red[64+tid]), fmaxf(red[128+tid], red[192+tid]));
        g_pmax[(b*24 + blockIdx.x)*64 + j] = mm;
    }
}

__global__ void k_final(const float* __restrict__ Wo1, const float* __restrict__ bo1,
                        const float* __restrict__ Wo2, const float* __restrict__ bo2,
                        const float* __restrict__ Wo3, const float* __restrict__ bo3,
                        float* __restrict__ out)
{
    __shared__ float pooled[64], o1[64], o2[64];
    int b = blockIdx.x, tid = threadIdx.x;
    float m = -3.0e38f;
#pragma unroll
    for (int p = 0; p < 24; p++) m = fmaxf(m, g_pmax[(b*24 + p)*64 + tid]);
    pooled[tid] = m;
    __syncthreads();
    {
        float s = bo1[tid];
#pragma unroll
        for (int d = 0; d < 64; d++) s += pooled[d] * Wo1[d*64 + tid];
        o1[tid] = elu_f(s);
    }
    __syncthreads();
    {
        float s = bo2[tid];
#pragma unroll
        for (int d = 0; d < 64; d++) s += o1[d] * Wo2[d*64 + tid];
        o2[tid] = elu_f(s);
    }
    __syncthreads();
    if (tid == 0) {
        float s = bo3[0];
#pragma unroll
        for (int d = 0; d < 64; d++) s += o2[d] * Wo3[d];
        out[b] = s;
    }
}

// ---------------------------------------------------------------- host
extern "C" void kernel_launch(void* const* d_in, const int* in_sizes, int n_in,
                              void* d_out, int out_size)
{
    const float* x   = (const float*)d_in[0];
    const float* dn  = (const float*)d_in[1];
    const float* Wi  = (const float*)d_in[2];
    const float* bi  = (const float*)d_in[3];
    const float* W1  = (const float*)d_in[4];
    const float* b1  = (const float*)d_in[5];
    const float* W2  = (const float*)d_in[6];
    const float* b2  = (const float*)d_in[7];
    const float* Wo1 = (const float*)d_in[8];
    const float* bo1 = (const float*)d_in[9];
    const float* Wo2 = (const float*)d_in[10];
    const float* bo2 = (const float*)d_in[11];
    const float* Wo3 = (const float*)d_in[12];
    const float* bo3 = (const float*)d_in[13];
    float* out = (float*)d_out;

    k_embed<<<BN*HDIM/256, 256>>>(x, dn, Wi, bi);

    for (int l = 0; l < 2; l++) {
        int src = l;
        int dst = 1 - l;
        k_ac   <<<BN/16, 1024>>>(src, W1 + l*128*128, b1 + l*128);
        k_knn  <<<dim3(NN/128, BQ, ZSPLIT), 128>>>(src);
        k_merge<<<(BN + 255)/256, 256>>>();
        k_edge <<<BN/4, 256>>>(dst, W2 + l*128*64, b2 + l*64);
    }
    k_pool <<<dim3(24, BQ), 256>>>();
    k_final<<<BQ, 64>>>(Wo1, bo1, Wo2, bo2, Wo3, bo3, out);
}